// round 8
// baseline (speedup 1.0000x reference)
#include <cuda_runtime.h>
#include <cuda_fp16.h>

// Problem constants (fixed by the dataset)
#define NB 8
#define NC 128
#define EO 48000
#define NU 8000
#define EN 72000            // EO + 3*NU
#define U2 16000            // 2*NU
#define NUNIT 32000         // EO - 2*NU (survivors)
#define NWE 40000           // 5*NU weighted entries

// smem: Ps f32[NUNIT] (128000 B) + Pw f16[NWE] (80000 B)
#define SMEM_BYTES (NUNIT * 4 + NWE * 2)   // 208000

// Weighted sub-slot bases within Pw (meta has bit31 set for these):
//   [0,NU)    lf*lw0   [NU,2NU)  lf*lw1   [2NU,3NU) rf*rw0
//   [3NU,4NU) rf*rw1   [4NU,5NU) 0.5*(lf*lw2 + rf*rw2)
#define W_L0 0
#define W_L1 NU
#define W_R0 (2*NU)
#define W_R1 (3*NU)
#define W_NW (4*NU)

// 4-byte gather meta: g_meta[b][j] = P index. s>=0 -> Ps[s]; s<0 -> Pw[s&0x7FFFFFFF]
__device__ __align__(16) int g_meta[NB * EN];
// Planar weights: g_wp[k][b*NU+u], k=0..5, 0.5 folded into k=2 and k=5
__device__ __align__(16) float g_wp[6 * NB * NU];

// Fused build: survivor meta + edge meta + planar weight transpose.
// All destination sets are disjoint slices of one permutation -> no ordering.
__global__ void k_build(const int* __restrict__ old_idx,
                        const float* __restrict__ weights,
                        const int* __restrict__ left_idx,
                        const int* __restrict__ right_idx,
                        const int* __restrict__ new_idx,
                        const int* __restrict__ new_left_idx,
                        const int* __restrict__ new_right_idx) {
    const int NBASE = NB * NUNIT / 4;   // 64000 : survivors, int4
    const int NEDGE = NB * NU / 4;      // 16000 : edges, int4 x5
    const int NWT   = NB * NU;          // 64000 : weight transpose
    int t = blockIdx.x * blockDim.x + threadIdx.x;
    if (t < NBASE) {
        int b = t / (NUNIT / 4);
        int r = t - b * (NUNIT / 4);
        int4 o = ((const int4*)old_idx)[b * (EO / 4) + (U2 / 4) + r];
        int e0 = 4 * r;                 // survivor index = e - 2U
        int base = b * EN;
        g_meta[base + o.x] = e0 + 0;
        g_meta[base + o.y] = e0 + 1;
        g_meta[base + o.z] = e0 + 2;
        g_meta[base + o.w] = e0 + 3;
    } else if (t < NBASE + NEDGE) {
        int t2 = t - NBASE;
        int b = t2 / (NU / 4);
        int r = t2 - b * (NU / 4);
        int u0 = 4 * r;
        int base = b * EN;
        int goff = b * (NU / 4) + r;
        const unsigned SB = 0x80000000u;
        int4 li  = ((const int4*)left_idx)[goff];
        int4 ri  = ((const int4*)right_idx)[goff];
        int4 ni  = ((const int4*)new_idx)[goff];
        int4 nli = ((const int4*)new_left_idx)[goff];
        int4 nri = ((const int4*)new_right_idx)[goff];
        g_meta[base + li.x]  = (int)(SB | (W_L0 + u0));
        g_meta[base + li.y]  = (int)(SB | (W_L0 + u0 + 1));
        g_meta[base + li.z]  = (int)(SB | (W_L0 + u0 + 2));
        g_meta[base + li.w]  = (int)(SB | (W_L0 + u0 + 3));
        g_meta[base + nli.x] = (int)(SB | (W_L1 + u0));
        g_meta[base + nli.y] = (int)(SB | (W_L1 + u0 + 1));
        g_meta[base + nli.z] = (int)(SB | (W_L1 + u0 + 2));
        g_meta[base + nli.w] = (int)(SB | (W_L1 + u0 + 3));
        g_meta[base + ri.x]  = (int)(SB | (W_R0 + u0));
        g_meta[base + ri.y]  = (int)(SB | (W_R0 + u0 + 1));
        g_meta[base + ri.z]  = (int)(SB | (W_R0 + u0 + 2));
        g_meta[base + ri.w]  = (int)(SB | (W_R0 + u0 + 3));
        g_meta[base + nri.x] = (int)(SB | (W_R1 + u0));
        g_meta[base + nri.y] = (int)(SB | (W_R1 + u0 + 1));
        g_meta[base + nri.z] = (int)(SB | (W_R1 + u0 + 2));
        g_meta[base + nri.w] = (int)(SB | (W_R1 + u0 + 3));
        g_meta[base + ni.x]  = (int)(SB | (W_NW + u0));
        g_meta[base + ni.y]  = (int)(SB | (W_NW + u0 + 1));
        g_meta[base + ni.z]  = (int)(SB | (W_NW + u0 + 2));
        g_meta[base + ni.w]  = (int)(SB | (W_NW + u0 + 3));
    } else if (t < NBASE + NEDGE + NWT) {
        int t2 = t - NBASE - NEDGE;     // = b*NU + u
        const float* w = weights + (size_t)t2 * 6;
        g_wp[0 * NWT + t2] = w[0];
        g_wp[1 * NWT + t2] = w[1];
        g_wp[2 * NWT + t2] = 0.5f * w[2];
        g_wp[3 * NWT + t2] = w[3];
        g_wp[4 * NWT + t2] = w[4];
        g_wp[5 * NWT + t2] = 0.5f * w[5];
    }
}

// Main kernel: one CTA per (b,c).
//  - Survivor block (128 KB, f32, exact) staged into smem via cp.async.cg
//    (fire-and-forget LDGSTS, no register roundtrip), overlapped with the
//    weighted f16 fill compute; drained with cp.async.wait_group.
//  - Gather: coalesced int4 meta (depth-2 prefetch), predicated dual-width
//    random smem loads, streaming float4 stores.
__global__ __launch_bounds__(1024)
void k_main(const float* __restrict__ features, float* __restrict__ out) {
    extern __shared__ float Ps[];               // [NUNIT] f32 survivors
    __half* Pw = (__half*)(Ps + NUNIT);         // [NWE] f16 weighted

    const int b = blockIdx.y;
    const int c = blockIdx.x;
    const int tid = threadIdx.x;
    const float* frow = features + (size_t)(b * NC + c) * EO;

    // Issue the survivor copy: 8000 float4 LDGSTS, ~8 per thread.
    {
        unsigned ps_a = (unsigned)__cvta_generic_to_shared(Ps);
        const float4* src = (const float4*)(frow + U2);
        #pragma unroll
        for (int i = tid; i < NUNIT / 4; i += 1024) {
            asm volatile("cp.async.cg.shared.global [%0], [%1], 16;"
                         :: "r"(ps_a + 16u * i), "l"(src + i) : "memory");
        }
        asm volatile("cp.async.commit_group;" ::: "memory");
    }

    // Weighted fill (overlaps with the async survivor copy).
    {
        const float4* lf4 = (const float4*)frow;
        const float4* rf4 = (const float4*)(frow + NU);
        const int wb = b * NU;
        const int NWT = NB * NU;
        #pragma unroll 2
        for (int i = tid; i < NU / 4; i += 1024) {
            float4 lf = __ldcs(lf4 + i);
            float4 rf = __ldcs(rf4 + i);
            int u = 4 * i;
            float4 a0 = *(const float4*)(g_wp + 0 * NWT + wb + u);
            float4 a1 = *(const float4*)(g_wp + 1 * NWT + wb + u);
            float4 a2 = *(const float4*)(g_wp + 2 * NWT + wb + u);
            float4 a3 = *(const float4*)(g_wp + 3 * NWT + wb + u);
            float4 a4 = *(const float4*)(g_wp + 4 * NWT + wb + u);
            float4 a5 = *(const float4*)(g_wp + 5 * NWT + wb + u);

            __half2* d;
            d = (__half2*)(Pw + W_L0 + u);
            d[0] = __floats2half2_rn(lf.x * a0.x, lf.y * a0.y);
            d[1] = __floats2half2_rn(lf.z * a0.z, lf.w * a0.w);
            d = (__half2*)(Pw + W_L1 + u);
            d[0] = __floats2half2_rn(lf.x * a1.x, lf.y * a1.y);
            d[1] = __floats2half2_rn(lf.z * a1.z, lf.w * a1.w);
            d = (__half2*)(Pw + W_R0 + u);
            d[0] = __floats2half2_rn(rf.x * a3.x, rf.y * a3.y);
            d[1] = __floats2half2_rn(rf.z * a3.z, rf.w * a3.w);
            d = (__half2*)(Pw + W_R1 + u);
            d[0] = __floats2half2_rn(rf.x * a4.x, rf.y * a4.y);
            d[1] = __floats2half2_rn(rf.z * a4.z, rf.w * a4.w);
            d = (__half2*)(Pw + W_NW + u);
            d[0] = __floats2half2_rn(fmaf(lf.x, a2.x, rf.x * a5.x),
                                     fmaf(lf.y, a2.y, rf.y * a5.y));
            d[1] = __floats2half2_rn(fmaf(lf.z, a2.z, rf.z * a5.z),
                                     fmaf(lf.w, a2.w, rf.w * a5.w));
        }
    }

    // Drain the async copy, then make everything visible CTA-wide.
    asm volatile("cp.async.wait_group 0;" ::: "memory");
    __syncthreads();

    // Gather with depth-2 rolling meta prefetch.
    const int4* m4 = (const int4*)(g_meta + b * EN);
    float4* o4 = (float4*)(out + (size_t)(b * NC + c) * EN);
    const int NQ = EN / 4;   // 18000

    int q = tid;
    int4 cur = __ldg(m4 + q);
    int qn = q + 1024;
    bool have = (qn < NQ);
    int4 nxt = have ? __ldg(m4 + qn) : cur;

    while (true) {
        int qpp = qn + 1024;
        bool have2 = have && (qpp < NQ);
        int4 n2 = have2 ? __ldg(m4 + qpp) : cur;

        float4 v;
        v.x = (cur.x >= 0) ? Ps[cur.x] : __half2float(Pw[cur.x & 0x7FFFFFFF]);
        v.y = (cur.y >= 0) ? Ps[cur.y] : __half2float(Pw[cur.y & 0x7FFFFFFF]);
        v.z = (cur.z >= 0) ? Ps[cur.z] : __half2float(Pw[cur.z & 0x7FFFFFFF]);
        v.w = (cur.w >= 0) ? Ps[cur.w] : __half2float(Pw[cur.w & 0x7FFFFFFF]);
        __stcs(o4 + q, v);

        if (!have) break;
        cur = nxt; q = qn;
        nxt = n2;  qn = qpp;
        have = have2;
    }
}

extern "C" void kernel_launch(void* const* d_in, const int* in_sizes, int n_in,
                              void* d_out, int out_size) {
    const float* features      = (const float*)d_in[0];
    const float* weights       = (const float*)d_in[1];
    const int*   old_idx       = (const int*)d_in[2];
    const int*   left_idx      = (const int*)d_in[3];
    const int*   right_idx     = (const int*)d_in[4];
    const int*   new_idx       = (const int*)d_in[5];
    const int*   new_left_idx  = (const int*)d_in[6];
    const int*   new_right_idx = (const int*)d_in[7];
    float* out = (float*)d_out;

    cudaFuncSetAttribute(k_main, cudaFuncAttributeMaxDynamicSharedMemorySize,
                         SMEM_BYTES);

    const int nbuild = NB * NUNIT / 4 + NB * NU / 4 + NB * NU;   // 144000
    k_build<<<(nbuild + 255) / 256, 256>>>(old_idx, weights, left_idx,
                                           right_idx, new_idx,
                                           new_left_idx, new_right_idx);
    dim3 grid(NC, NB);
    k_main<<<grid, 1024, SMEM_BYTES>>>(features, out);
}

// round 10
// speedup vs baseline: 1.2324x; 1.2324x over previous
#include <cuda_runtime.h>
#include <cuda_fp16.h>

// Problem constants (fixed by the dataset)
#define NB 8
#define NC 128
#define EO 48000
#define NU 8000
#define EN 72000            // EO + 3*NU
#define U2 16000            // 2*NU
#define NUNIT 32000         // EO - 2*NU (survivors)

// Uniform f16 P array, 72000 entries, 144000 B smem:
//   [0,32000)       : feat[2U + i]              (survivors)
//   [32000,40000)   : lf*lw0      [40000,48000) : lf*lw1
//   [48000,56000)   : rf*rw0      [56000,64000) : rf*rw1
//   [64000,72000)   : 0.5*(lf*lw2 + rf*rw2)
#define S_L0 32000
#define S_L1 40000
#define S_R0 48000
#define S_R1 56000
#define S_NW 64000

#define SMEM_BYTES (EN * 2)   // 144000

// 4-byte gather meta: g_meta[b][j] = P index (single uniform path).
__device__ __align__(16) int g_meta[NB * EN];
// Planar weights: g_wp[k][b*NU+u], k=0..5, 0.5 folded into k=2 and k=5
__device__ __align__(16) float g_wp[6 * NB * NU];

// Fused build: survivor meta + edge meta + planar weight transpose.
// All five destination sets are disjoint slices of one permutation ->
// every j written exactly once, no ordering needed.
__global__ void k_build(const int* __restrict__ old_idx,
                        const float* __restrict__ weights,
                        const int* __restrict__ left_idx,
                        const int* __restrict__ right_idx,
                        const int* __restrict__ new_idx,
                        const int* __restrict__ new_left_idx,
                        const int* __restrict__ new_right_idx) {
    const int NBASE = NB * NUNIT / 4;   // 64000 : survivors, int4
    const int NEDGE = NB * NU / 4;      // 16000 : edges, int4 x5
    const int NWT   = NB * NU;          // 64000 : weight transpose
    int t = blockIdx.x * blockDim.x + threadIdx.x;
    if (t < NBASE) {
        int b = t / (NUNIT / 4);
        int r = t - b * (NUNIT / 4);
        int4 o = ((const int4*)old_idx)[b * (EO / 4) + (U2 / 4) + r];
        int e0 = 4 * r;                 // P index = e - 2U
        int base = b * EN;
        g_meta[base + o.x] = e0 + 0;
        g_meta[base + o.y] = e0 + 1;
        g_meta[base + o.z] = e0 + 2;
        g_meta[base + o.w] = e0 + 3;
    } else if (t < NBASE + NEDGE) {
        int t2 = t - NBASE;
        int b = t2 / (NU / 4);
        int r = t2 - b * (NU / 4);
        int u0 = 4 * r;
        int base = b * EN;
        int goff = b * (NU / 4) + r;
        int4 li  = ((const int4*)left_idx)[goff];
        int4 ri  = ((const int4*)right_idx)[goff];
        int4 ni  = ((const int4*)new_idx)[goff];
        int4 nli = ((const int4*)new_left_idx)[goff];
        int4 nri = ((const int4*)new_right_idx)[goff];
        g_meta[base + li.x]  = S_L0 + u0;     g_meta[base + li.y]  = S_L0 + u0 + 1;
        g_meta[base + li.z]  = S_L0 + u0 + 2; g_meta[base + li.w]  = S_L0 + u0 + 3;
        g_meta[base + nli.x] = S_L1 + u0;     g_meta[base + nli.y] = S_L1 + u0 + 1;
        g_meta[base + nli.z] = S_L1 + u0 + 2; g_meta[base + nli.w] = S_L1 + u0 + 3;
        g_meta[base + ri.x]  = S_R0 + u0;     g_meta[base + ri.y]  = S_R0 + u0 + 1;
        g_meta[base + ri.z]  = S_R0 + u0 + 2; g_meta[base + ri.w]  = S_R0 + u0 + 3;
        g_meta[base + nri.x] = S_R1 + u0;     g_meta[base + nri.y] = S_R1 + u0 + 1;
        g_meta[base + nri.z] = S_R1 + u0 + 2; g_meta[base + nri.w] = S_R1 + u0 + 3;
        g_meta[base + ni.x]  = S_NW + u0;     g_meta[base + ni.y]  = S_NW + u0 + 1;
        g_meta[base + ni.z]  = S_NW + u0 + 2; g_meta[base + ni.w]  = S_NW + u0 + 3;
    } else if (t < NBASE + NEDGE + NWT) {
        int t2 = t - NBASE - NEDGE;     // = b*NU + u
        const float* w = weights + (size_t)t2 * 6;
        g_wp[0 * NWT + t2] = w[0];
        g_wp[1 * NWT + t2] = w[1];
        g_wp[2 * NWT + t2] = 0.5f * w[2];
        g_wp[3 * NWT + t2] = w[3];
        g_wp[4 * NWT + t2] = w[4];
        g_wp[5 * NWT + t2] = 0.5f * w[5];
    }
}

// Main kernel: one CTA per (b,c). Uniform f16 P fill (vectorized, planar
// weights), then gather with pair-processing + rolling meta prefetch:
// coalesced int4 meta, 1 random LDS.16 per output, streaming float4 stores.
__global__ __launch_bounds__(1024)
void k_main(const float* __restrict__ features, float* __restrict__ out) {
    extern __shared__ __half P[];
    const int b = blockIdx.y;
    const int c = blockIdx.x;
    const int tid = threadIdx.x;
    const float* frow = features + (size_t)(b * NC + c) * EO;

    // Survivors: feat[2U..EO) -> P[0..32000), float4 reads, half2 writes.
    {
        const float4* f4 = (const float4*)(frow + U2);
        __half2* p2 = (__half2*)P;
        #pragma unroll 4
        for (int i = tid; i < NUNIT / 4; i += 1024) {
            float4 f = __ldcs(f4 + i);
            p2[2 * i]     = __floats2half2_rn(f.x, f.y);
            p2[2 * i + 1] = __floats2half2_rn(f.z, f.w);
        }
    }
    // Weighted entries from planar weights (coalesced float4 streams).
    {
        const float4* lf4 = (const float4*)frow;
        const float4* rf4 = (const float4*)(frow + NU);
        const int wb = b * NU;
        const int NWT = NB * NU;
        #pragma unroll 2
        for (int i = tid; i < NU / 4; i += 1024) {
            float4 lf = __ldcs(lf4 + i);
            float4 rf = __ldcs(rf4 + i);
            int u = 4 * i;
            float4 a0 = *(const float4*)(g_wp + 0 * NWT + wb + u);
            float4 a1 = *(const float4*)(g_wp + 1 * NWT + wb + u);
            float4 a2 = *(const float4*)(g_wp + 2 * NWT + wb + u);
            float4 a3 = *(const float4*)(g_wp + 3 * NWT + wb + u);
            float4 a4 = *(const float4*)(g_wp + 4 * NWT + wb + u);
            float4 a5 = *(const float4*)(g_wp + 5 * NWT + wb + u);

            __half2* d;
            d = (__half2*)(P + S_L0 + u);
            d[0] = __floats2half2_rn(lf.x * a0.x, lf.y * a0.y);
            d[1] = __floats2half2_rn(lf.z * a0.z, lf.w * a0.w);
            d = (__half2*)(P + S_L1 + u);
            d[0] = __floats2half2_rn(lf.x * a1.x, lf.y * a1.y);
            d[1] = __floats2half2_rn(lf.z * a1.z, lf.w * a1.w);
            d = (__half2*)(P + S_R0 + u);
            d[0] = __floats2half2_rn(rf.x * a3.x, rf.y * a3.y);
            d[1] = __floats2half2_rn(rf.z * a3.z, rf.w * a3.w);
            d = (__half2*)(P + S_R1 + u);
            d[0] = __floats2half2_rn(rf.x * a4.x, rf.y * a4.y);
            d[1] = __floats2half2_rn(rf.z * a4.z, rf.w * a4.w);
            d = (__half2*)(P + S_NW + u);
            d[0] = __floats2half2_rn(fmaf(lf.x, a2.x, rf.x * a5.x),
                                     fmaf(lf.y, a2.y, rf.y * a5.y));
            d[1] = __floats2half2_rn(fmaf(lf.z, a2.z, rf.z * a5.z),
                                     fmaf(lf.w, a2.w, rf.w * a5.w));
        }
    }
    __syncthreads();

    // Gather: pairs (q, q+1024) per iteration, rolling prefetch of next pair.
    const int4* m4 = (const int4*)(g_meta + b * EN);
    float4* o4 = (float4*)(out + (size_t)(b * NC + c) * EN);
    const int NQ = EN / 4;      // 18000
    const int STRIDE = 2048;

    int q = tid;
    int4 s0 = __ldg(m4 + q);            // q < 1024 < NQ always
    int4 s1 = __ldg(m4 + q + 1024);     // q+1024 < 2048 < NQ always

    while (true) {
        int qa = q + STRIDE;
        int qb = qa + 1024;
        bool ha = qa < NQ;
        bool hb = qb < NQ;
        int4 p0 = ha ? __ldg(m4 + qa) : s0;
        int4 p1 = hb ? __ldg(m4 + qb) : s1;

        float4 v0;
        v0.x = __half2float(P[s0.x]);
        v0.y = __half2float(P[s0.y]);
        v0.z = __half2float(P[s0.z]);
        v0.w = __half2float(P[s0.w]);
        __stcs(o4 + q, v0);

        if (q + 1024 < NQ) {
            float4 v1;
            v1.x = __half2float(P[s1.x]);
            v1.y = __half2float(P[s1.y]);
            v1.z = __half2float(P[s1.z]);
            v1.w = __half2float(P[s1.w]);
            __stcs(o4 + q + 1024, v1);
        }

        if (!ha) break;
        s0 = p0; s1 = p1; q = qa;
    }
}

extern "C" void kernel_launch(void* const* d_in, const int* in_sizes, int n_in,
                              void* d_out, int out_size) {
    const float* features      = (const float*)d_in[0];
    const float* weights       = (const float*)d_in[1];
    const int*   old_idx       = (const int*)d_in[2];
    const int*   left_idx      = (const int*)d_in[3];
    const int*   right_idx     = (const int*)d_in[4];
    const int*   new_idx       = (const int*)d_in[5];
    const int*   new_left_idx  = (const int*)d_in[6];
    const int*   new_right_idx = (const int*)d_in[7];
    float* out = (float*)d_out;

    cudaFuncSetAttribute(k_main, cudaFuncAttributeMaxDynamicSharedMemorySize,
                         SMEM_BYTES);

    const int nbuild = NB * NUNIT / 4 + NB * NU / 4 + NB * NU;   // 144000
    k_build<<<(nbuild + 255) / 256, 256>>>(old_idx, weights, left_idx,
                                           right_idx, new_idx,
                                           new_left_idx, new_right_idx);
    dim3 grid(NC, NB);
    k_main<<<grid, 1024, SMEM_BYTES>>>(features, out);
}